// round 7
// baseline (speedup 1.0000x reference)
#include <cuda_runtime.h>
#include <cstdint>

#define BATCH 4
#define C_IN 32
#define C_OUT 32
#define NNODE 163842
#define K7 7

#define TM 128                           // nodes per CTA
#define THREADS 128                      // 4 warps
#define NT2 ((NNODE + TM - 1) / TM)      // 1281

// ---- global scratch (no cudaMalloc allowed) ----
__device__ float g_xt[(size_t)BATCH * NNODE * C_IN];   // x transposed [B,N,32]
// Per-slot fragment-ordered W images: [j][hi 1024 fl | lo 1024 fl]
__device__ float g_wimg[K7 * 2048];
__constant__ float cB[C_OUT];

// ---- smem layout (bytes) ----
#define SM_RAW   0            // 2 bufs x 16384 (A fp32 -> hi in place)
#define SM_LO    32768        // 2 bufs x 16384 (A lo)
#define SM_W     65536        // 2 bufs x 8192  (W hi+lo fragment images)
#define SM_SIDX  81920        // 128*7 ints = 3584
#define SM_TOTAL 85504

// ---------------------------------------------------------------------------
// helpers
// ---------------------------------------------------------------------------
__device__ __forceinline__ uint32_t s2u(const void* p) {
    uint32_t a;
    asm("{ .reg .u64 t; cvta.to.shared.u64 t, %1; cvt.u32.u64 %0, t; }"
        : "=r"(a) : "l"(p));
    return a;
}
#define CP_ASYNC4(d, s)  asm volatile("cp.async.ca.shared.global [%0], [%1], 4;"  :: "r"(d), "l"(s))
#define CP_ASYNC16(d, s) asm volatile("cp.async.cg.shared.global [%0], [%1], 16;" :: "r"(d), "l"(s))
#define CP_COMMIT()      asm volatile("cp.async.commit_group;")
#define CP_WAIT(n)       asm volatile("cp.async.wait_group %0;" :: "n"(n))

__device__ __forceinline__ uint32_t tf32_rna(float x) {
    uint32_t r;
    asm("cvt.rna.tf32.f32 %0, %1;" : "=r"(r) : "f"(x));
    return r;
}

// mma.sync m16n8k8 tf32: D += A*B (fp32 accum), register fragments.
__device__ __forceinline__ void mma_tf32(float* d, const uint32_t* a,
                                         const uint32_t* b) {
    asm volatile(
        "mma.sync.aligned.m16n8k8.row.col.f32.tf32.tf32.f32 "
        "{%0,%1,%2,%3}, {%4,%5,%6,%7}, {%8,%9}, {%0,%1,%2,%3};"
        : "+f"(d[0]), "+f"(d[1]), "+f"(d[2]), "+f"(d[3])
        : "r"(a[0]), "r"(a[1]), "r"(a[2]), "r"(a[3]), "r"(b[0]), "r"(b[1]));
}

// ---------------------------------------------------------------------------
// Kernel 1: transpose x [B, C_IN, N] -> xt [B, N, C_IN]
// ---------------------------------------------------------------------------
__global__ __launch_bounds__(256) void transpose_kernel(const float* __restrict__ x,
                                                        float* __restrict__ xt) {
    __shared__ float tile[32][33];
    const int b = blockIdx.y;
    const int n0 = blockIdx.x * 32;
    const int tx = threadIdx.x, ty = threadIdx.y;
    const int n_ld = n0 + tx;
#pragma unroll
    for (int c = ty; c < 32; c += 8) {
        float v = 0.0f;
        if (n_ld < NNODE) v = x[((size_t)b * C_IN + c) * NNODE + n_ld];
        tile[c][tx] = v;
    }
    __syncthreads();
#pragma unroll
    for (int r = ty; r < 32; r += 8) {
        const int n = n0 + r;
        if (n < NNODE) xt[((size_t)b * NNODE + n) * C_IN + tx] = tile[tx][r];
    }
}

// Kernel 1b: split W [32][224] into per-slot fragment-ordered (hi, lo) images.
// B fragment (m16n8k8, col): element (k, n) -> lane = (n&7)*4 + (k&3), reg = k>>2.
__global__ __launch_bounds__(256) void wsplit_kernel(const float* __restrict__ W,
                                                     float* __restrict__ wimg) {
    const int i = blockIdx.x * 256 + threadIdx.x;
    if (i >= 32 * 224) return;
    const int o = i / 224, k = i % 224;
    const int j = k / 32, kk = k % 32;
    const int ks = kk >> 3, kc = kk & 7;
    const int nb = o >> 3;
    const int lane = (o & 7) * 4 + (kc & 3);
    const int reg = kc >> 2;
    const float a = W[i];
    const uint32_t hb = tf32_rna(a);
    const float hf = __uint_as_float(hb);
    const uint32_t lb = tf32_rna(a - hf);
    const int base = j * 2048 + ((ks * 4 + nb) * 32 + lane) * 2 + reg;
    wimg[base] = __uint_as_float(hb);
    wimg[base + 1024] = __uint_as_float(lb);
}

// ---------------------------------------------------------------------------
// Kernel 2: tensor-core conv via mma.sync tf32 (3-term hi/lo split).
// CTA = 4 warps x 128 nodes; warp w -> rows [w*32, w*32+32), all 32 outs.
// ---------------------------------------------------------------------------
__global__ __launch_bounds__(THREADS, 2) void onering_conv_mma_kernel(
    const float* __restrict__ xt,
    const int* __restrict__ neigh,
    const float* __restrict__ wimg,
    float* __restrict__ out) {

    extern __shared__ __align__(16) char smem[];
    const uint32_t sbase = s2u(smem);
    int* sidx = (int*)(smem + SM_SIDX);

    const int tid  = threadIdx.x;
    const int wid  = tid >> 5;
    const int lane = tid & 31;
    const int b    = blockIdx.y;
    const int n0   = blockIdx.x * TM;

#pragma unroll
    for (int i = tid; i < TM * K7; i += THREADS) {
        const int gg = n0 * K7 + i;
        sidx[i] = (gg < NNODE * K7) ? neigh[gg] : 0;
    }
    __syncthreads();

    const float* xb = xt + (size_t)b * NNODE * C_IN;

    // Per-lane constant parts of the A-fragment address (lane = k within slot).
    // Element (r, kk): ks = kk>>3, c = kk&7; frag lane = (r&7)*4 + (c&3),
    // reg = (r>>3 of the 16-row block) + 2*(c>>2); block = r>>4 (0..7).
    const int g_ks   = lane >> 3;
    const int g_c3   = lane & 3;         // (kk&7)&3 == lane&3
    const int g_creg = 2 * ((lane >> 2) & 1);

    // Gather ring slot j into A raw buf + W images buf.
    auto gather = [&](int j, int buf) {
        const uint32_t abase = sbase + SM_RAW + buf * 16384;
#pragma unroll
        for (int r = wid; r < TM; r += 4) {
            const int m = sidx[r * K7 + j];
            const int blk = r >> 4;
            const int rr = r & 15;
            const int lane_f = (rr & 7) * 4 + g_c3;
            const int reg = (rr >> 3) + g_creg;
            const uint32_t off = (uint32_t)(((blk * 4 + g_ks) * 32 + lane_f) * 16
                                            + reg * 4);
            CP_ASYNC4(abase + off, xb + (size_t)m * C_IN + lane);
        }
        const uint32_t wdst = sbase + SM_W + buf * 8192;
        const float* wsrc = wimg + j * 2048;
#pragma unroll
        for (int i = tid; i < 512; i += THREADS)
            CP_ASYNC16(wdst + i * 16, wsrc + i * 4);
    };

    // In-place hi/lo tf32 split (element-wise, layout-agnostic).
    auto convert = [&](int buf) {
        float4* raw4 = (float4*)(smem + SM_RAW + buf * 16384);
        float4* lo4  = (float4*)(smem + SM_LO + buf * 16384);
#pragma unroll
        for (int i = 0; i < 8; i++) {
            const int c = tid + i * THREADS;
            float4 v = raw4[c];
            float4 h, l;
            h.x = __uint_as_float(tf32_rna(v.x)); l.x = __uint_as_float(tf32_rna(v.x - h.x));
            h.y = __uint_as_float(tf32_rna(v.y)); l.y = __uint_as_float(tf32_rna(v.y - h.y));
            h.z = __uint_as_float(tf32_rna(v.z)); l.z = __uint_as_float(tf32_rna(v.z - h.z));
            h.w = __uint_as_float(tf32_rna(v.w)); l.w = __uint_as_float(tf32_rna(v.w - h.w));
            raw4[c] = h;
            lo4[c]  = l;
        }
    };

    float d[2][4][4];   // [mb][nb][reg]
#pragma unroll
    for (int mb = 0; mb < 2; mb++)
#pragma unroll
        for (int nb = 0; nb < 4; nb++)
#pragma unroll
            for (int q = 0; q < 4; q++) d[mb][nb][q] = 0.0f;

    gather(0, 0);
    CP_COMMIT();

#pragma unroll 1
    for (int j = 0; j < K7; j++) {
        const int buf = j & 1;
        if (j + 1 < K7) {
            gather(j + 1, buf ^ 1);
            CP_COMMIT();
            CP_WAIT(1);
        } else {
            CP_WAIT(0);
        }
        __syncthreads();

        convert(buf);
        __syncthreads();

        const uint32_t ah_base = sbase + SM_RAW + buf * 16384;
        const uint32_t al_base = sbase + SM_LO + buf * 16384;
        const uint32_t w_base  = sbase + SM_W + buf * 8192;

#pragma unroll
        for (int mb = 0; mb < 2; mb++) {
            const int blk = wid * 2 + mb;
#pragma unroll
            for (int ks = 0; ks < 4; ks++) {
                const uint32_t aoff = (uint32_t)(((blk * 4 + ks) * 32 + lane) * 16);
                uint32_t ah[4], al[4];
                asm("ld.shared.v4.b32 {%0,%1,%2,%3}, [%4];"
                    : "=r"(ah[0]), "=r"(ah[1]), "=r"(ah[2]), "=r"(ah[3])
                    : "r"(ah_base + aoff));
                asm("ld.shared.v4.b32 {%0,%1,%2,%3}, [%4];"
                    : "=r"(al[0]), "=r"(al[1]), "=r"(al[2]), "=r"(al[3])
                    : "r"(al_base + aoff));
#pragma unroll
                for (int nb = 0; nb < 4; nb++) {
                    const uint32_t boff = (uint32_t)(((ks * 4 + nb) * 32 + lane) * 8);
                    uint32_t bh[2], bl[2];
                    asm("ld.shared.v2.b32 {%0,%1}, [%2];"
                        : "=r"(bh[0]), "=r"(bh[1]) : "r"(w_base + boff));
                    asm("ld.shared.v2.b32 {%0,%1}, [%2];"
                        : "=r"(bl[0]), "=r"(bl[1]) : "r"(w_base + boff + 4096));
                    mma_tf32(d[mb][nb], ah, bh);
                    mma_tf32(d[mb][nb], al, bh);
                    mma_tf32(d[mb][nb], ah, bl);
                }
            }
        }
        __syncthreads();   // all reads of buf done before it is re-gathered
    }

    // Epilogue. D element (r, o2): reg = (r>>3)*2 + (o2&1); r_lo = lane>>2,
    // cols o = nb*8 + 2*(lane&3) (+1).
    const int r_lo = lane >> 2;
    const int c0   = 2 * (lane & 3);
#pragma unroll
    for (int mb = 0; mb < 2; mb++) {
        const int nb_row = n0 + wid * 32 + mb * 16;
#pragma unroll
        for (int nb = 0; nb < 4; nb++) {
            const int o = nb * 8 + c0;
#pragma unroll
            for (int half = 0; half < 2; half++) {
                const int n = nb_row + r_lo + half * 8;
                if (n < NNODE) {
                    float* ob = out + (size_t)b * C_OUT * NNODE + n;
                    ob[(size_t)o * NNODE]       = d[mb][nb][half * 2]     + cB[o];
                    ob[(size_t)(o + 1) * NNODE] = d[mb][nb][half * 2 + 1] + cB[o + 1];
                }
            }
        }
    }
}

// ---------------------------------------------------------------------------
// Launch
// ---------------------------------------------------------------------------
extern "C" void kernel_launch(void* const* d_in, const int* in_sizes, int n_in,
                              void* d_out, int out_size) {
    const float* x     = (const float*)d_in[0];
    const float* W     = (const float*)d_in[1];
    const float* bias  = (const float*)d_in[2];
    const int*   neigh = (const int*)d_in[3];
    float* out = (float*)d_out;

    float* xt = nullptr;
    cudaGetSymbolAddress((void**)&xt, g_xt);
    float* wimg = nullptr;
    cudaGetSymbolAddress((void**)&wimg, g_wimg);

    {
        dim3 block(32, 8);
        dim3 grid((NNODE + 31) / 32, BATCH);
        transpose_kernel<<<grid, block>>>(x, xt);
    }
    wsplit_kernel<<<(32 * 224 + 255) / 256, 256>>>(W, wimg);
    cudaMemcpyToSymbolAsync(cB, bias, C_OUT * sizeof(float), 0,
                            cudaMemcpyDeviceToDevice, 0);
    {
        cudaFuncSetAttribute(onering_conv_mma_kernel,
                             cudaFuncAttributeMaxDynamicSharedMemorySize, SM_TOTAL);
        dim3 grid(NT2, BATCH);
        onering_conv_mma_kernel<<<grid, THREADS, SM_TOTAL>>>(xt, neigh, wimg, out);
    }
}

// round 8
// speedup vs baseline: 1.5676x; 1.5676x over previous
#include <cuda_runtime.h>
#include <cstdint>

#define BATCH 4
#define C_IN 32
#define C_OUT 32
#define NNODE 163842
#define K7 7

#define TM 128                           // nodes per CTA
#define THREADS 128                      // 4 warps
#define NT2 ((NNODE + TM - 1) / TM)      // 1281
#define PITCH 36                         // A row pitch in floats (144B)

// ---- global scratch ----
__device__ float g_xt[(size_t)BATCH * NNODE * C_IN];   // x transposed [B,N,32]
// W fragment images, hi/lo interleaved per 16B: [j][ks][nb][lane][bh0 bh1 bl0 bl1]
__device__ float g_wimg[K7 * 16 * 32 * 4];             // 14336 floats = 56KB
__constant__ float cB[C_OUT];

// ---- smem layout (bytes) ----
#define SM_A     0                        // 2 bufs x TM x PITCH x 4 = 36864
#define SM_W     36864                    // 57344
#define SM_SIDX  94208                    // 128*7 ints = 3584
#define SM_TOTAL 97792

// ---------------------------------------------------------------------------
// helpers
// ---------------------------------------------------------------------------
__device__ __forceinline__ uint32_t s2u(const void* p) {
    uint32_t a;
    asm("{ .reg .u64 t; cvta.to.shared.u64 t, %1; cvt.u32.u64 %0, t; }"
        : "=r"(a) : "l"(p));
    return a;
}
#define CP_ASYNC16(d, s) asm volatile("cp.async.cg.shared.global [%0], [%1], 16;" :: "r"(d), "l"(s))
#define CP_COMMIT()      asm volatile("cp.async.commit_group;")
#define CP_WAIT(n)       asm volatile("cp.async.wait_group %0;" :: "n"(n))

__device__ __forceinline__ uint32_t tf32_rna(float x) {
    uint32_t r;
    asm("cvt.rna.tf32.f32 %0, %1;" : "=r"(r) : "f"(x));
    return r;
}
// In-register split: hi (tf32 bits, valid fp32), lo = tf32(x - hi)
__device__ __forceinline__ void split_tf32(float x, uint32_t& hi, uint32_t& lo) {
    hi = tf32_rna(x);
    lo = tf32_rna(x - __uint_as_float(hi));
}

__device__ __forceinline__ void mma_tf32(float* d, const uint32_t* a,
                                         uint32_t b0, uint32_t b1) {
    asm volatile(
        "mma.sync.aligned.m16n8k8.row.col.f32.tf32.tf32.f32 "
        "{%0,%1,%2,%3}, {%4,%5,%6,%7}, {%8,%9}, {%0,%1,%2,%3};"
        : "+f"(d[0]), "+f"(d[1]), "+f"(d[2]), "+f"(d[3])
        : "r"(a[0]), "r"(a[1]), "r"(a[2]), "r"(a[3]), "r"(b0), "r"(b1));
}

// ---------------------------------------------------------------------------
// Kernel 1: transpose x [B, C_IN, N] -> xt [B, N, C_IN]
// ---------------------------------------------------------------------------
__global__ __launch_bounds__(256) void transpose_kernel(const float* __restrict__ x,
                                                        float* __restrict__ xt) {
    __shared__ float tile[32][33];
    const int b = blockIdx.y;
    const int n0 = blockIdx.x * 32;
    const int tx = threadIdx.x, ty = threadIdx.y;
    const int n_ld = n0 + tx;
#pragma unroll
    for (int c = ty; c < 32; c += 8) {
        float v = 0.0f;
        if (n_ld < NNODE) v = x[((size_t)b * C_IN + c) * NNODE + n_ld];
        tile[c][tx] = v;
    }
    __syncthreads();
#pragma unroll
    for (int r = ty; r < 32; r += 8) {
        const int n = n0 + r;
        if (n < NNODE) xt[((size_t)b * NNODE + n) * C_IN + tx] = tile[tx][r];
    }
}

// Kernel 1b: split W [32][224] into fragment-ordered images, hi/lo interleaved.
// Element (o, k): j=k/32, kk=k%32, ks=kk>>3, kc=kk&7, nb=o>>3;
// lane=(o&7)*4+(kc&3); reg=kc>>2. Slot = [((j*16+ks*4+nb)*32+lane)*4 + {reg, 2+reg}]
__global__ __launch_bounds__(256) void wsplit_kernel(const float* __restrict__ W,
                                                     float* __restrict__ wimg) {
    const int i = blockIdx.x * 256 + threadIdx.x;
    if (i >= 32 * 224) return;
    const int o = i / 224, k = i % 224;
    const int j = k / 32, kk = k % 32;
    const int ks = kk >> 3, kc = kk & 7;
    const int nb = o >> 3;
    const int lane = (o & 7) * 4 + (kc & 3);
    const int reg = kc >> 2;
    uint32_t hb, lb;
    split_tf32(W[i], hb, lb);
    const int base = ((j * 16 + ks * 4 + nb) * 32 + lane) * 4;
    wimg[base + reg]     = __uint_as_float(hb);
    wimg[base + 2 + reg] = __uint_as_float(lb);
}

// ---------------------------------------------------------------------------
// Kernel 2: mma.sync tf32 conv, 3-term hi/lo split in registers.
// CTA = 4 warps x 128 nodes; warp w -> rows [w*32, w*32+32), all 32 outs.
// A gathered row-major (pitch 36 fl) via 16B cp.async; W images static in smem.
// ---------------------------------------------------------------------------
__global__ __launch_bounds__(THREADS, 2) void onering_conv_mma_kernel(
    const float* __restrict__ xt,
    const int* __restrict__ neigh,
    const float* __restrict__ wimg,
    float* __restrict__ out) {

    extern __shared__ __align__(16) char smem[];
    const uint32_t sbase = s2u(smem);
    int* sidx = (int*)(smem + SM_SIDX);

    const int tid  = threadIdx.x;
    const int wid  = tid >> 5;
    const int lane = tid & 31;
    const int b    = blockIdx.y;
    const int n0   = blockIdx.x * TM;

#pragma unroll
    for (int i = tid; i < TM * K7; i += THREADS) {
        const int gg = n0 * K7 + i;
        sidx[i] = (gg < NNODE * K7) ? neigh[gg] : 0;
    }
    __syncthreads();

    const float* xb = xt + (size_t)b * NNODE * C_IN;
    const int rsub = lane >> 3, seg = lane & 7;

    // Gather ring slot j into A buffer `buf` (row-major, 8x16B per row).
    auto gather = [&](int j, int buf) {
        const uint32_t abase = sbase + SM_A + buf * (TM * PITCH * 4);
#pragma unroll
        for (int it = 0; it < 8; it++) {
            const int r = it * 16 + wid * 4 + rsub;
            const int m = sidx[r * K7 + j];
            CP_ASYNC16(abase + (uint32_t)(r * (PITCH * 4) + seg * 16),
                       xb + (size_t)m * C_IN + seg * 4);
        }
    };

    // Prologue: W images (56KB) + first gather in one cp.async group.
#pragma unroll
    for (int i = tid; i < 3584; i += THREADS)
        CP_ASYNC16(sbase + SM_W + i * 16, wimg + i * 4);
    gather(0, 0);
    CP_COMMIT();

    float d[2][4][4];
#pragma unroll
    for (int mb = 0; mb < 2; mb++)
#pragma unroll
        for (int nb = 0; nb < 4; nb++)
#pragma unroll
            for (int q = 0; q < 4; q++) d[mb][nb][q] = 0.0f;

    const int g  = lane >> 2;
    const int c4 = lane & 3;

#pragma unroll 1
    for (int j = 0; j < K7; j++) {
        const int buf = j & 1;
        if (j + 1 < K7) {
            gather(j + 1, buf ^ 1);
            CP_COMMIT();
            CP_WAIT(1);
        } else {
            CP_WAIT(0);
        }
        __syncthreads();

        // Load + split all 8 A fragments into registers.
        uint32_t ah[2][4][4], al[2][4][4];
        const uint32_t ab = sbase + SM_A + buf * (TM * PITCH * 4);
#pragma unroll
        for (int mb = 0; mb < 2; mb++) {
            const int rb = wid * 32 + mb * 16;
#pragma unroll
            for (int ks = 0; ks < 4; ks++) {
                const uint32_t a0 = ab + (uint32_t)(((rb + g) * PITCH + ks * 8 + c4) * 4);
                float r0, r1, r2, r3;
                asm("ld.shared.f32 %0, [%1];" : "=f"(r0) : "r"(a0));
                asm("ld.shared.f32 %0, [%1];" : "=f"(r2) : "r"(a0 + 16));
                asm("ld.shared.f32 %0, [%1];" : "=f"(r1) : "r"(a0 + 8 * PITCH * 4));
                asm("ld.shared.f32 %0, [%1];" : "=f"(r3) : "r"(a0 + 8 * PITCH * 4 + 16));
                split_tf32(r0, ah[mb][ks][0], al[mb][ks][0]);
                split_tf32(r1, ah[mb][ks][1], al[mb][ks][1]);
                split_tf32(r2, ah[mb][ks][2], al[mb][ks][2]);
                split_tf32(r3, ah[mb][ks][3], al[mb][ks][3]);
            }
        }
        __syncthreads();   // all warps done reading buf before it's re-gathered

        // MMA: W fragments hoisted over mb; one LDS.128 per (ks, nb).
        const uint32_t wbase = sbase + SM_W + (uint32_t)(j * 16 * 32 * 16);
#pragma unroll
        for (int ks = 0; ks < 4; ks++) {
#pragma unroll
            for (int nb = 0; nb < 4; nb++) {
                uint32_t w0, w1, w2, w3;
                asm("ld.shared.v4.b32 {%0,%1,%2,%3}, [%4];"
                    : "=r"(w0), "=r"(w1), "=r"(w2), "=r"(w3)
                    : "r"(wbase + (uint32_t)(((ks * 4 + nb) * 32 + lane) * 16)));
#pragma unroll
                for (int mb = 0; mb < 2; mb++) {
                    mma_tf32(d[mb][nb], ah[mb][ks], w0, w1);
                    mma_tf32(d[mb][nb], al[mb][ks], w0, w1);
                    mma_tf32(d[mb][nb], ah[mb][ks], w2, w3);
                }
            }
        }
    }

    // Epilogue: D (r, o): regs {0,1} -> row lane>>2, {2,3} -> +8; col 2*(lane&3)+{0,1}
    const int r_lo = lane >> 2;
    const int c0   = 2 * (lane & 3);
#pragma unroll
    for (int mb = 0; mb < 2; mb++) {
        const int nrow = n0 + wid * 32 + mb * 16;
#pragma unroll
        for (int nb = 0; nb < 4; nb++) {
            const int o = nb * 8 + c0;
#pragma unroll
            for (int half = 0; half < 2; half++) {
                const int n = nrow + r_lo + half * 8;
                if (n < NNODE) {
                    float* ob = out + (size_t)b * C_OUT * NNODE + n;
                    ob[(size_t)o * NNODE]       = d[mb][nb][half * 2]     + cB[o];
                    ob[(size_t)(o + 1) * NNODE] = d[mb][nb][half * 2 + 1] + cB[o + 1];
                }
            }
        }
    }
}

// ---------------------------------------------------------------------------
// Launch
// ---------------------------------------------------------------------------
extern "C" void kernel_launch(void* const* d_in, const int* in_sizes, int n_in,
                              void* d_out, int out_size) {
    const float* x     = (const float*)d_in[0];
    const float* W     = (const float*)d_in[1];
    const float* bias  = (const float*)d_in[2];
    const int*   neigh = (const int*)d_in[3];
    float* out = (float*)d_out;

    float* xt = nullptr;
    cudaGetSymbolAddress((void**)&xt, g_xt);
    float* wimg = nullptr;
    cudaGetSymbolAddress((void**)&wimg, g_wimg);

    {
        dim3 block(32, 8);
        dim3 grid((NNODE + 31) / 32, BATCH);
        transpose_kernel<<<grid, block>>>(x, xt);
    }
    wsplit_kernel<<<(32 * 224 + 255) / 256, 256>>>(W, wimg);
    cudaMemcpyToSymbolAsync(cB, bias, C_OUT * sizeof(float), 0,
                            cudaMemcpyDeviceToDevice, 0);
    {
        cudaFuncSetAttribute(onering_conv_mma_kernel,
                             cudaFuncAttributeMaxDynamicSharedMemorySize, SM_TOTAL);
        dim3 grid(NT2, BATCH);
        onering_conv_mma_kernel<<<grid, THREADS, SM_TOTAL>>>(xt, neigh, wimg, out);
    }
}